// round 3
// baseline (speedup 1.0000x reference)
#include <cuda_runtime.h>
#include <cstdint>

#define CCH   33
#define NPATCH 36
#define KSZ   2112      // 33*8*8
#define FEAT  107
#define IMG   65536     // 256*256

// SHIFTS / 255 exactly as the reference table (note duplicated [0,8] at j=6)
__constant__ float c_shift[9][2] = {
  {-8.f/255.f,  0.f/255.f}, {-8.f/255.f,  8.f/255.f}, { 0.f/255.f,  8.f/255.f},
  { 8.f/255.f,  8.f/255.f}, { 8.f/255.f,  0.f/255.f}, { 8.f/255.f, -8.f/255.f},
  { 0.f/255.f,  8.f/255.f}, {-8.f/255.f, -8.f/255.f}, { 0.f/255.f,  0.f/255.f}
};

// scratch: patch_feat [32][36][33]
__device__ float g_patch_feat[32 * 36 * 33];

// ---------------------------------------------------------------------------
// threefry2x32 (JAX-compatible, 20 rounds)
// ---------------------------------------------------------------------------
__device__ __forceinline__ void threefry2x32(uint32_t k0, uint32_t k1,
                                             uint32_t x0, uint32_t x1,
                                             uint32_t& o0, uint32_t& o1)
{
  uint32_t ks[3] = {k0, k1, k0 ^ k1 ^ 0x1BD11BDAu};
  x0 += ks[0]; x1 += ks[1];
  const int R[2][4] = {{13, 15, 26, 6}, {17, 29, 16, 24}};
#pragma unroll
  for (int i = 0; i < 5; ++i) {
#pragma unroll
    for (int r = 0; r < 4; ++r) {
      x0 += x1;
      int rr = R[i & 1][r];
      x1 = (x1 << rr) | (x1 >> (32 - rr));
      x1 ^= x0;
    }
    x0 += ks[(i + 1) % 3];
    x1 += ks[(i + 2) % 3] + (uint32_t)(i + 1);
  }
  o0 = x0; o1 = x1;
}

// uniform[0,1) float per JAX partitionable threefry: counts (hi=0, lo=g), bits = y0^y1
__device__ __forceinline__ float tf_uniform(uint32_t k0, uint32_t k1, uint32_t g)
{
  uint32_t y0, y1;
  threefry2x32(k0, k1, 0u, g, y0, y1);
  uint32_t bits = y0 ^ y1;
  return __uint_as_float((bits >> 9) | 0x3f800000u) - 1.0f;
}

// ---------------------------------------------------------------------------
// Kernel A: crops + full-contraction conv. grid (9, 32) — 4 patches per block.
// ---------------------------------------------------------------------------
__global__ __launch_bounds__(256)
void crop_conv_kernel(const float* __restrict__ d, const float* __restrict__ x,
                      const float* __restrict__ conv_w, const float* __restrict__ conv_b)
{
  const int pg = blockIdx.x;   // patch group 0..8 (4 crops each)
  const int b  = blockIdx.y;   // batch
  const int tid = threadIdx.x;

  __shared__ float crop[4 * KSZ];
  __shared__ int s_ix[4], s_iy[4];

  if (tid == 0) {
    // faithful sequential simulation of lh (exact fp addition order)
    float lh[NPATCH][2];
    for (int n = 0; n < NPATCH; ++n) {
      lh[n][0] = x[b * 8 + (n / 9) * 2 + 0];
      lh[n][1] = x[b * 8 + (n / 9) * 2 + 1];
    }
    for (int st = 0; st < 36; ++st) {
      int i = st / 9, j = st % 9, idx = i * j;
      lh[idx][0] += c_shift[j][0];
      lh[idx][1] += c_shift[j][1];
      int rel = st - pg * 4;
      if (rel >= 0 && rel < 4) {
        int ix = (int)rintf(lh[idx][0] * 255.f);
        int iy = (int)rintf((lh[idx][1] + 1.0f) * 255.f);
        s_ix[rel] = min(max(ix, 0), 255);
        s_iy[rel] = min(max(iy, 0), 255);
      }
    }
  }
  __syncthreads();

  const float* db = d + (size_t)b * CCH * IMG;
#pragma unroll
  for (int q = 0; q < 4; ++q) {
    int ix = s_ix[q], iy = s_iy[q];
    for (int k = tid; k < KSZ; k += 256) {
      int c = k >> 6, h = (k >> 3) & 7, w = k & 7;
      int r  = ix - 4 + h;
      int cc = iy - 4 + w;
      float v = 0.f;
      if ((unsigned)r < 256u && (unsigned)cc < 256u)
        v = db[c * IMG + r * 256 + cc];
      crop[q * KSZ + k] = v;
    }
  }
  __syncthreads();

  const int warp = tid >> 5, lane = tid & 31;
  // warp handles outputs o = warp + 8t; warp 0 additionally gets o=32
  float acc[5][4];
#pragma unroll
  for (int t = 0; t < 5; ++t)
#pragma unroll
    for (int q = 0; q < 4; ++q) acc[t][q] = 0.f;

  for (int k = lane; k < KSZ; k += 32) {
    float c0 = crop[k];
    float c1 = crop[KSZ + k];
    float c2 = crop[2 * KSZ + k];
    float c3 = crop[3 * KSZ + k];
#pragma unroll
    for (int t = 0; t < 4; ++t) {
      float w = conv_w[(warp + t * 8) * KSZ + k];
      acc[t][0] += c0 * w; acc[t][1] += c1 * w;
      acc[t][2] += c2 * w; acc[t][3] += c3 * w;
    }
    if (warp == 0) {
      float w = conv_w[32 * KSZ + k];
      acc[4][0] += c0 * w; acc[4][1] += c1 * w;
      acc[4][2] += c2 * w; acc[4][3] += c3 * w;
    }
  }

#pragma unroll
  for (int t = 0; t < 5; ++t) {
    int o = warp + t * 8;
    if (o >= 33) break;
#pragma unroll
    for (int q = 0; q < 4; ++q) {
      float s = acc[t][q];
#pragma unroll
      for (int off = 16; off; off >>= 1) s += __shfl_xor_sync(0xffffffffu, s, off);
      if (lane == 0)
        g_patch_feat[((size_t)b * 36 + pg * 4 + q) * 33 + o] = s + conv_b[o];
    }
  }
}

// ---------------------------------------------------------------------------
// Kernel B: gin assembly, hypergraph MP, dropout, heads. 1 block / batch.
// ---------------------------------------------------------------------------
__global__ __launch_bounds__(128)
void tail_kernel(const float* __restrict__ x,
                 const float* __restrict__ H,  const float* __restrict__ T,
                 const float* __restrict__ W,
                 const float* __restrict__ l1w, const float* __restrict__ l1b,
                 const float* __restrict__ l2w, const float* __restrict__ l2b,
                 float* __restrict__ out)
{
  const int b = blockIdx.x, tid = threadIdx.x;

  __shared__ float lh[36][2];
  __shared__ float gin[36 * FEAT];
  __shared__ float A[4][16];
  __shared__ float M1[4][36];
  __shared__ float x1s[4 * FEAT], x2s[4 * FEAT];
  __shared__ float logit[4][9];
  __shared__ float off[4][2];
  __shared__ uint32_t skeys[4];

  if (tid == 0) {
    float l[36][2];
    for (int n = 0; n < 36; ++n) {
      l[n][0] = x[b * 8 + (n / 9) * 2 + 0];
      l[n][1] = x[b * 8 + (n / 9) * 2 + 1];
    }
    for (int st = 0; st < 36; ++st) {
      int i = st / 9, j = st % 9, idx = i * j;
      l[idx][0] += c_shift[j][0];
      l[idx][1] += c_shift[j][1];
    }
    for (int n = 0; n < 36; ++n) { lh[n][0] = l[n][0]; lh[n][1] = l[n][1]; }
    // k1, k2 = split(key(42))  [partitionable/foldlike]
    uint32_t a0, a1;
    threefry2x32(0u, 42u, 0u, 0u, a0, a1); skeys[0] = a0; skeys[1] = a1;
    threefry2x32(0u, 42u, 0u, 1u, a0, a1); skeys[2] = a0; skeys[3] = a1;
  }
  __syncthreads();

  // gin = [patch_feat(33) | shape_feat(72) | lh(2)]
  for (int e = tid; e < 36 * FEAT; e += 128) {
    int n = e / FEAT, f = e % FEAT;
    float v;
    if (f < 33)        v = g_patch_feat[((size_t)b * 36 + n) * 33 + f];
    else if (f < 105) { int m = (f - 33) >> 1, k = (f - 33) & 1; v = lh[m][k] - lh[n][k]; }
    else               v = lh[n][f - 105];
    gin[e] = v;
  }

  // A = T @ (H * W)
  if (tid < 64) {
    int p = tid >> 4, h = tid & 15;
    float s = 0.f;
    float wh = W[h];
    for (int n = 0; n < 36; ++n) s += T[p * 36 + n] * (H[n * 16 + h] * wh);
    A[p][h] = s;
  }
  __syncthreads();

  // M1 = A @ H^T  (144 entries — MUST stride, block has 128 threads)
  for (int e = tid; e < 144; e += 128) {
    int p = e / 36, n = e % 36;
    float s = 0.f;
    for (int h = 0; h < 16; ++h) s += A[p][h] * H[n * 16 + h];
    M1[p][n] = s;
  }
  __syncthreads();

  // message + deterministic dropout
  const uint32_t k10 = skeys[0], k11 = skeys[1], k20 = skeys[2], k21 = skeys[3];
  for (int e = tid; e < 4 * FEAT; e += 128) {
    int p = e / FEAT, f = e % FEAT;
    float s = 0.f;
    for (int n = 0; n < 36; ++n) s += M1[p][n] * gin[n * FEAT + f];
    uint32_t g = (uint32_t)((b * 4 + p) * FEAT + f);
    float u1 = tf_uniform(k10, k11, g);
    float u2 = tf_uniform(k20, k21, g);
    x1s[e] = (u1 < 0.9f) ? s / 0.9f : 0.f;
    x2s[e] = (u2 < 0.9f) ? s / 0.9f : 0.f;
  }
  __syncthreads();

  // offset = sigmoid(x1 @ l1w^T + l1b)
  if (tid < 8) {
    int p = tid >> 1, k = tid & 1;
    float s = l1b[k];
    for (int f = 0; f < FEAT; ++f) s += x1s[p * FEAT + f] * l1w[k * FEAT + f];
    off[p][k] = 1.f / (1.f + expf(-s));
  }
  // logits = x2 @ l2w^T + l2b
  if (tid >= 32 && tid < 68) {
    int e = tid - 32, p = e / 9, j = e % 9;
    float s = l2b[j];
    for (int f = 0; f < FEAT; ++f) s += x2s[p * FEAT + f] * l2w[j * FEAT + f];
    logit[p][j] = s;
  }
  __syncthreads();

  if (tid < 4) {
    int p = tid;
    float mx = logit[p][0];
#pragma unroll
    for (int j = 1; j < 9; ++j) mx = fmaxf(mx, logit[p][j]);
    float ex[9]; float den = 0.f;
#pragma unroll
    for (int j = 0; j < 9; ++j) { ex[j] = expf(logit[p][j] - mx); den += ex[j]; }
    float s0 = 0.f, s1 = 0.f;
#pragma unroll
    for (int j = 0; j < 9; ++j) {
      float dj = ex[j] / den;
      s0 += dj * c_shift[j][0];
      s1 += dj * c_shift[j][1];
    }
    out[b * 8 + p * 2 + 0] = (x[b * 8 + p * 2 + 0] + off[p][0] * s0) * 255.f;
    out[b * 8 + p * 2 + 1] = (x[b * 8 + p * 2 + 1] + off[p][1] * s1) * 255.f;
  }
}

// ---------------------------------------------------------------------------
extern "C" void kernel_launch(void* const* d_in, const int* in_sizes, int n_in,
                              void* d_out, int out_size)
{
  const float* d      = (const float*)d_in[0];
  const float* x      = (const float*)d_in[1];
  const float* conv_w = (const float*)d_in[2];
  const float* conv_b = (const float*)d_in[3];
  const float* H      = (const float*)d_in[4];
  const float* T      = (const float*)d_in[5];
  const float* W      = (const float*)d_in[6];
  const float* l1w    = (const float*)d_in[7];
  const float* l1b    = (const float*)d_in[8];
  const float* l2w    = (const float*)d_in[9];
  const float* l2b    = (const float*)d_in[10];
  float* out = (float*)d_out;

  dim3 gridA(9, 32);
  crop_conv_kernel<<<gridA, 256>>>(d, x, conv_w, conv_b);
  tail_kernel<<<32, 128>>>(x, H, T, W, l1w, l1b, l2w, l2b, out);
}